// round 6
// baseline (speedup 1.0000x reference)
#include <cuda_runtime.h>
#include <cstdint>

#define N_USERS 50000
#define N_ITEMS 100000
#define N_NODES 150000
#define NNZ     1000000
#define D       64
#define ND      (N_NODES * D)      /* 9,600,000 */
#define N_HOPS  3
#define CAP     32                 /* max kept in-edges per row per hop */

// keep message iff bits < 0xE6666600  (== u01(bits) < 0.9f exactly)
#define MSG_TH  0xE6666600u

#define NB_INIT 9375               /* ND/4/256 exact */
#define NB_EDGE 977                /* ceil(NNZ/4 / 256) */

// Scratch (no cudaMalloc allowed)
__device__ float g_agg[2][ND];                       // ping-pong agg buffers
__device__ uint2 g_slots[N_HOPS][N_NODES * CAP];     // per-row edge bins (val,col)
__device__ int   g_deg[N_HOPS][N_NODES];             // per-row kept-degree cursors
                                                     // (0 at module load; each
                                                     // gather resets its hop)

// ---------------------------------------------------------------------------
// JAX threefry2x32.  Host version (key derivation) + device version with adds
// on the fma pipe (IMAD via runtime-opaque multiplier `one`).
// ---------------------------------------------------------------------------
__host__ __forceinline__ uint32_t rotl32h(uint32_t x, int r) {
    return (x << r) | (x >> (32 - r));
}

__host__ void threefry2x32_host(uint32_t k0, uint32_t k1, uint32_t x0, uint32_t x1,
                                uint32_t& o0, uint32_t& o1)
{
    uint32_t ks2 = k0 ^ k1 ^ 0x1BD11BDAu;
    x0 += k0; x1 += k1;
#define TF_R4(a,b,c,d)                                   \
    x0 += x1; x1 = rotl32h(x1,(a)); x1 ^= x0;            \
    x0 += x1; x1 = rotl32h(x1,(b)); x1 ^= x0;            \
    x0 += x1; x1 = rotl32h(x1,(c)); x1 ^= x0;            \
    x0 += x1; x1 = rotl32h(x1,(d)); x1 ^= x0;
    TF_R4(13,15,26,6);   x0 += k1;  x1 += ks2 + 1u;
    TF_R4(17,29,16,24);  x0 += ks2; x1 += k0  + 2u;
    TF_R4(13,15,26,6);   x0 += k0;  x1 += k1  + 3u;
    TF_R4(17,29,16,24);  x0 += k1;  x1 += ks2 + 4u;
    TF_R4(13,15,26,6);   x0 += ks2; x1 += k0  + 5u;
#undef TF_R4
    o0 = x0; o1 = x1;
}

__device__ __forceinline__ uint32_t addi(uint32_t a, uint32_t b, uint32_t one) {
    uint32_t d;
    asm("mad.lo.u32 %0, %1, %2, %3;" : "=r"(d) : "r"(a), "r"(one), "r"(b));
    return d;
}

__device__ __forceinline__ uint32_t rotxor(uint32_t x, int r, uint32_t y) {
    return __funnelshift_l(x, x, (unsigned)r) ^ y;
}

__device__ __forceinline__ void tf_round4(uint32_t& x0, uint32_t& x1,
                                          int a, int b, int c, int d,
                                          uint32_t one)
{
    x0 = addi(x0, x1, one); x1 = rotxor(x1, a, x0);
    x0 = addi(x0, x1, one); x1 = rotxor(x1, b, x0);
    x0 = addi(x0, x1, one); x1 = rotxor(x1, c, x0);
    x0 = addi(x0, x1, one); x1 = rotxor(x1, d, x0);
}

// Partitionable-mode random bits at flat index i: block (0, i), bits = o0^o1.
__device__ __forceinline__ uint32_t tf_bits_i(uint32_t k0, uint32_t k1,
                                              uint32_t ks2, uint32_t i,
                                              uint32_t one)
{
    uint32_t x0 = k0;                 // 0 + k0
    uint32_t x1 = addi(i, k1, one);
    tf_round4(x0, x1, 13, 15, 26,  6, one);
    x0 = addi(x0, k1,  one); x1 = addi(x1, ks2 + 1u, one);
    tf_round4(x0, x1, 17, 29, 16, 24, one);
    x0 = addi(x0, ks2, one); x1 = addi(x1, k0  + 2u, one);
    tf_round4(x0, x1, 13, 15, 26,  6, one);
    x0 = addi(x0, k0,  one); x1 = addi(x1, k1  + 3u, one);
    tf_round4(x0, x1, 17, 29, 16, 24, one);
    x0 = addi(x0, k1,  one); x1 = addi(x1, ks2 + 4u, one);
    tf_round4(x0, x1, 13, 15, 26,  6, one);
    x0 = addi(x0, ks2, one); x1 = addi(x1, k0  + 5u, one);
    return x0 ^ x1;
}

// ---------------------------------------------------------------------------
// Kernel 1: init (out hop-0 slice) + edge dropout with per-row binning for
// all 3 hops.  Disjoint block ranges.  g_deg is zero at entry (module load /
// reset by previous call's gather kernels).
// ---------------------------------------------------------------------------
__global__ void k_init_edge(const float4* __restrict__ ue,
                            const float4* __restrict__ ie,
                            float4* __restrict__ out,
                            const float4* __restrict__ vals,
                            const int4*  __restrict__ rows,
                            const int4*  __restrict__ cols,
                            uint32_t ke00, uint32_t ke01,
                            uint32_t ke10, uint32_t ke11,
                            uint32_t ke20, uint32_t ke21,
                            uint32_t one)
{
    int blk = blockIdx.x;
    if (blk < NB_INIT) {
        // out hop-0 slice <- concat(user,item)
        int i = blk * blockDim.x + threadIdx.x;   // over ND/4, exact
        int node = i >> 4;
        int q    = i & 15;
        float4 v = (node < N_USERS) ? ue[node * 16 + q]
                                    : ie[(node - N_USERS) * 16 + q];
        out[(size_t)node * 64 + q] = v;
        return;
    }

    // edge dropout + row binning, 4 edges/thread, 3 hops
    int t = (blk - NB_INIT) * blockDim.x + threadIdx.x;
    if (t >= NNZ / 4) return;

    float4 v  = vals[t];
    int4   rr = rows[t];
    int4   cc = cols[t];
    float vv[4] = {v.x, v.y, v.z, v.w};
    int   ra[4] = {rr.x, rr.y, rr.z, rr.w};
    int   ca[4] = {cc.x, cc.y, cc.z, cc.w};
    uint32_t j  = (uint32_t)t * 4u;

    uint32_t K0[3] = {ke00, ke10, ke20};
    uint32_t K1[3] = {ke01, ke11, ke21};

#pragma unroll
    for (int h = 0; h < N_HOPS; h++) {
        uint32_t ks2 = K0[h] ^ K1[h] ^ 0x1BD11BDAu;
#pragma unroll
        for (int i = 0; i < 4; i++) {
            uint32_t b = tf_bits_i(K0[h], K1[h], ks2, j + (uint32_t)i, one);
            if ((int)b < 0) {                     // keep: u >= 0.5
                int r   = ra[i];
                int pos = atomicAdd(&g_deg[h][r], 1);
                if (pos < CAP)
                    g_slots[h][(size_t)r * CAP + pos] =
                        make_uint2(__float_as_uint(vv[i] * 2.0f), (uint32_t)ca[i]);
            }
        }
    }
}

// ---------------------------------------------------------------------------
// Kernel 2 (per hop): fused gather-SpMM + message dropout + emit.
// 16 threads per destination node; chunk-of-4 pipelined gathers; RNG hides
// gather latency.  Resets g_deg[hop][n] for the next graph replay.
// ---------------------------------------------------------------------------
__global__ void k_gather(const float4* __restrict__ ue,
                         const float4* __restrict__ ie,
                         int src, int dst, int hop,
                         float4* __restrict__ out,
                         uint32_t k0, uint32_t k1, uint32_t one)
{
    int g = blockIdx.x * blockDim.x + threadIdx.x;   // N_NODES*16 exact
    int n = g >> 4;
    int t = g & 15;

    int deg = g_deg[hop][n];
    __syncwarp();                     // all 16 owners read before reset
    if (t == 0) g_deg[hop][n] = 0;    // consumed; zero for next replay
    if (deg > CAP) deg = CAP;

    const uint2*  sl = g_slots[hop] + (size_t)n * CAP;
    const float4* A  = (const float4*)g_agg[src];

    float4 acc = make_float4(0.f, 0.f, 0.f, 0.f);
    for (int e0 = 0; e0 < deg; e0 += 4) {
        uint2 m[4];
        float4 gr[4];
#pragma unroll
        for (int i = 0; i < 4; i++)
            if (e0 + i < deg) m[i] = sl[e0 + i];
#pragma unroll
        for (int i = 0; i < 4; i++) {
            if (e0 + i < deg) {
                int c = (int)m[i].y;
                const float4* p;
                if (hop == 0)
                    p = (c < N_USERS) ? (ue + (size_t)c * 16)
                                      : (ie + (size_t)(c - N_USERS) * 16);
                else
                    p = A + (size_t)c * 16;
                gr[i] = p[t];
            }
        }
#pragma unroll
        for (int i = 0; i < 4; i++) {
            if (e0 + i < deg) {
                float v = __uint_as_float(m[i].x);
                acc.x += v * gr[i].x;
                acc.y += v * gr[i].y;
                acc.z += v * gr[i].z;
                acc.w += v * gr[i].w;
            }
        }
    }

    // message dropout on this thread's 4 elements (flat idx = n*64 + t*4 + i).
    // If the row aggregated to zero (deg==0), dropout of 0 is 0 -> skip RNG.
    float4 r = make_float4(0.f, 0.f, 0.f, 0.f);
    if (deg > 0) {
        uint32_t ks2 = k0 ^ k1 ^ 0x1BD11BDAu;
        uint32_t j = (uint32_t)n * 64u + (uint32_t)t * 4u;
        uint32_t b0 = tf_bits_i(k0, k1, ks2, j + 0u, one);
        uint32_t b1 = tf_bits_i(k0, k1, ks2, j + 1u, one);
        uint32_t b2 = tf_bits_i(k0, k1, ks2, j + 2u, one);
        uint32_t b3 = tf_bits_i(k0, k1, ks2, j + 3u, one);
        const float s = 1.0f / 0.9f;
        r.x = (b0 < MSG_TH) ? acc.x * s : 0.0f;
        r.y = (b1 < MSG_TH) ? acc.y * s : 0.0f;
        r.z = (b2 < MSG_TH) ? acc.z * s : 0.0f;
        r.w = (b3 < MSG_TH) ? acc.w * s : 0.0f;
    }

    if (dst >= 0)
        ((float4*)g_agg[dst])[(size_t)n * 16 + t] = r;
    out[(size_t)n * 64 + (size_t)(hop + 1) * 16 + t] = r;
}

// ---------------------------------------------------------------------------
// Launch
// ---------------------------------------------------------------------------
extern "C" void kernel_launch(void* const* d_in, const int* in_sizes, int n_in,
                              void* d_out, int out_size)
{
    const float4* ue   = (const float4*)d_in[0];
    const float4* ie   = (const float4*)d_in[1];
    const int4*   rows = (const int4*)d_in[2];
    const int4*   cols = (const int4*)d_in[3];
    const float4* vals = (const float4*)d_in[4];
    float*        out  = (float*)d_out;

    // Partitionable ("fold-like") split: split(key,3)[i] = threefry(key, (0,i))
    uint32_t key0 = 0u, key1 = 42u;   // jax.random.key(42)
    uint32_t ke[N_HOPS][2], km[N_HOPS][2];
    for (int h = 0; h < N_HOPS; h++) {
        uint32_t n0, n1;
        threefry2x32_host(key0, key1, 0u, 0u, n0, n1);
        threefry2x32_host(key0, key1, 0u, 1u, ke[h][0], ke[h][1]);
        threefry2x32_host(key0, key1, 0u, 2u, km[h][0], km[h][1]);
        key0 = n0; key1 = n1;
    }

    const int B = 256;
    const uint32_t one = 1u;   // runtime-opaque multiplier for IMAD adds

    k_init_edge<<<NB_INIT + NB_EDGE, B>>>(ue, ie, (float4*)out,
                                          vals, rows, cols,
                                          ke[0][0], ke[0][1],
                                          ke[1][0], ke[1][1],
                                          ke[2][0], ke[2][1], one);

    // hop0: src=inputs -> agg0;  hop1: agg0 -> agg1;  hop2: agg1 -> out only
    int srcs[3] = {0, 0, 1};    // hop0 src ignored (gathers ue/ie)
    int dsts[3] = {0, 1, -1};
    for (int h = 0; h < N_HOPS; h++) {
        k_gather<<<(N_NODES * 16) / B, B>>>(ue, ie, srcs[h], dsts[h], h,
                                            (float4*)out, km[h][0], km[h][1], one);
    }
}

// round 7
// speedup vs baseline: 1.6063x; 1.6063x over previous
#include <cuda_runtime.h>
#include <cstdint>

#define N_USERS 50000
#define N_ITEMS 100000
#define N_NODES 150000
#define NNZ     1000000
#define D       64
#define ND      (N_NODES * D)      /* 9,600,000 */
#define N_HOPS  3

// keep message iff bits < 0xE6666600  (== u01(bits) < 0.9f exactly)
#define MSG_TH  0xE6666600u

#define NB_INIT 9375               /* ND/4/256 exact */
#define NB_EDGE 977                /* ceil(NNZ/4 / 256) */
#define EPG     8                  /* edges per 16-thread group in spmm */
#define CAP_EDGES 540672           /* kept-edge cap (expected 500k, ~80 sigma) */
#define NB_SPMM ((CAP_EDGES / EPG) * 16 / 256)   /* 4224 blocks */
#define NB_DROP 4688               /* ceil(1,200,000 / 256) */

// Scratch (no cudaMalloc allowed)
__device__ int4 g_edges[N_HOPS][NNZ];   // compacted kept edges {row, col, valbits, 0}
__device__ int  g_cnt[4];               // per-hop kept-edge counters (0 at module
                                        // load; last k_drop re-zeroes -> replay-safe)

// ---------------------------------------------------------------------------
// JAX threefry2x32.  Host version (key derivation) + device version with adds
// on the fma pipe (IMAD via runtime-opaque multiplier `one`).
// ---------------------------------------------------------------------------
__host__ __forceinline__ uint32_t rotl32h(uint32_t x, int r) {
    return (x << r) | (x >> (32 - r));
}

__host__ void threefry2x32_host(uint32_t k0, uint32_t k1, uint32_t x0, uint32_t x1,
                                uint32_t& o0, uint32_t& o1)
{
    uint32_t ks2 = k0 ^ k1 ^ 0x1BD11BDAu;
    x0 += k0; x1 += k1;
#define TF_R4(a,b,c,d)                                   \
    x0 += x1; x1 = rotl32h(x1,(a)); x1 ^= x0;            \
    x0 += x1; x1 = rotl32h(x1,(b)); x1 ^= x0;            \
    x0 += x1; x1 = rotl32h(x1,(c)); x1 ^= x0;            \
    x0 += x1; x1 = rotl32h(x1,(d)); x1 ^= x0;
    TF_R4(13,15,26,6);   x0 += k1;  x1 += ks2 + 1u;
    TF_R4(17,29,16,24);  x0 += ks2; x1 += k0  + 2u;
    TF_R4(13,15,26,6);   x0 += k0;  x1 += k1  + 3u;
    TF_R4(17,29,16,24);  x0 += k1;  x1 += ks2 + 4u;
    TF_R4(13,15,26,6);   x0 += ks2; x1 += k0  + 5u;
#undef TF_R4
    o0 = x0; o1 = x1;
}

__device__ __forceinline__ uint32_t addi(uint32_t a, uint32_t b, uint32_t one) {
    uint32_t d;
    asm("mad.lo.u32 %0, %1, %2, %3;" : "=r"(d) : "r"(a), "r"(one), "r"(b));
    return d;
}

__device__ __forceinline__ uint32_t rotxor(uint32_t x, int r, uint32_t y) {
    return __funnelshift_l(x, x, (unsigned)r) ^ y;
}

__device__ __forceinline__ void tf_round4(uint32_t& x0, uint32_t& x1,
                                          int a, int b, int c, int d,
                                          uint32_t one)
{
    x0 = addi(x0, x1, one); x1 = rotxor(x1, a, x0);
    x0 = addi(x0, x1, one); x1 = rotxor(x1, b, x0);
    x0 = addi(x0, x1, one); x1 = rotxor(x1, c, x0);
    x0 = addi(x0, x1, one); x1 = rotxor(x1, d, x0);
}

// Partitionable-mode random bits at flat index i: block (0, i), bits = o0^o1.
__device__ __forceinline__ uint32_t tf_bits_i(uint32_t k0, uint32_t k1,
                                              uint32_t ks2, uint32_t i,
                                              uint32_t one)
{
    uint32_t x0 = k0;                 // 0 + k0
    uint32_t x1 = addi(i, k1, one);
    tf_round4(x0, x1, 13, 15, 26,  6, one);
    x0 = addi(x0, k1,  one); x1 = addi(x1, ks2 + 1u, one);
    tf_round4(x0, x1, 17, 29, 16, 24, one);
    x0 = addi(x0, ks2, one); x1 = addi(x1, k0  + 2u, one);
    tf_round4(x0, x1, 13, 15, 26,  6, one);
    x0 = addi(x0, k0,  one); x1 = addi(x1, k1  + 3u, one);
    tf_round4(x0, x1, 17, 29, 16, 24, one);
    x0 = addi(x0, k1,  one); x1 = addi(x1, ks2 + 4u, one);
    tf_round4(x0, x1, 13, 15, 26,  6, one);
    x0 = addi(x0, ks2, one); x1 = addi(x1, k0  + 5u, one);
    return x0 ^ x1;
}

// ---------------------------------------------------------------------------
// Kernel 1: init out (slice0 = embeddings, slices 1-3 = 0) + edge dropout
// with compaction for all 3 hops.  Disjoint block ranges.
// ---------------------------------------------------------------------------
__global__ void k_init_edge(const float4* __restrict__ ue,
                            const float4* __restrict__ ie,
                            float4* __restrict__ out,
                            const float4* __restrict__ vals,
                            const int4*  __restrict__ rows,
                            const int4*  __restrict__ cols,
                            uint32_t ke00, uint32_t ke01,
                            uint32_t ke10, uint32_t ke11,
                            uint32_t ke20, uint32_t ke21,
                            uint32_t one)
{
    int blk = blockIdx.x;
    if (blk < NB_INIT) {
        // out[node][0][*] <- embed; out[node][1..3][*] <- 0
        int i = blk * blockDim.x + threadIdx.x;   // over ND/4, exact
        int node = i >> 4;
        int q    = i & 15;
        float4 v = (node < N_USERS) ? ue[node * 16 + q]
                                    : ie[(node - N_USERS) * 16 + q];
        size_t o = (size_t)node * 64 + q;
        float4 z = make_float4(0.f, 0.f, 0.f, 0.f);
        out[o]      = v;
        out[o + 16] = z;
        out[o + 32] = z;
        out[o + 48] = z;
        return;
    }

    // edge dropout + compaction, 4 edges/thread, all 3 hops
    int t    = (blk - NB_INIT) * blockDim.x + threadIdx.x;
    int lane = threadIdx.x & 31;
    bool live = (t < NNZ / 4);

    float4 v  = make_float4(0.f, 0.f, 0.f, 0.f);
    int4   rr = make_int4(0, 0, 0, 0), cc = make_int4(0, 0, 0, 0);
    if (live) { v = vals[t]; rr = rows[t]; cc = cols[t]; }
    float vv[4] = {v.x, v.y, v.z, v.w};
    int   ra[4] = {rr.x, rr.y, rr.z, rr.w};
    int   ca[4] = {cc.x, cc.y, cc.z, cc.w};
    uint32_t j  = (uint32_t)t * 4u;

    uint32_t K0[3] = {ke00, ke10, ke20};
    uint32_t K1[3] = {ke01, ke11, ke21};

#pragma unroll
    for (int h = 0; h < N_HOPS; h++) {
        uint32_t ks2 = K0[h] ^ K1[h] ^ 0x1BD11BDAu;
        int4 e[4];
        int kept = 0;
        if (live) {
#pragma unroll
            for (int i = 0; i < 4; i++) {
                uint32_t b = tf_bits_i(K0[h], K1[h], ks2, j + (uint32_t)i, one);
                if ((int)b < 0) {                     // keep: u >= 0.5
                    e[kept] = make_int4(ra[i], ca[i],
                                        __float_as_int(vv[i] * 2.0f), 0);
                    kept++;
                }
            }
        }
        // warp inclusive scan of kept
        int off = kept;
#pragma unroll
        for (int d = 1; d < 32; d <<= 1) {
            int nn = __shfl_up_sync(0xFFFFFFFFu, off, d);
            if (lane >= d) off += nn;
        }
        int total = __shfl_sync(0xFFFFFFFFu, off, 31);
        int base  = 0;
        if (lane == 31 && total > 0) base = atomicAdd(&g_cnt[h], total);
        base = __shfl_sync(0xFFFFFFFFu, base, 31);

        int pos = base + off - kept;
#pragma unroll
        for (int i = 0; i < 4; i++)
            if (i < kept) g_edges[h][pos + i] = e[i];
    }
}

// ---------------------------------------------------------------------------
// Kernel 2 (per hop): SpMM scatter over compacted edges, directly on out.
// 16 threads per group of EPG=8 edges: batched meta loads -> 8 independent
// gathers (slice hop) -> 8 vector reds (slice hop+1).
// ---------------------------------------------------------------------------
__global__ void k_spmm(float4* __restrict__ out, int hop)
{
    unsigned g  = blockIdx.x * blockDim.x + threadIdx.x;
    int      eg = (int)(g >> 4);
    int      t  = (int)(g & 15);
    int count = g_cnt[hop];
    int base  = eg * EPG;
    if (base >= count) return;
    int n = count - base; if (n > EPG) n = EPG;

    const int4* E = g_edges[hop];
    int4 m[EPG];
#pragma unroll
    for (int i = 0; i < EPG; i++)
        if (i < n) m[i] = E[base + i];

    float4 a[EPG];
#pragma unroll
    for (int i = 0; i < EPG; i++)
        if (i < n) a[i] = out[(size_t)m[i].y * 64 + hop * 16 + t];

#pragma unroll
    for (int i = 0; i < EPG; i++) {
        if (i < n) {
            float v = __int_as_float(m[i].z);
            float4* d = out + (size_t)m[i].x * 64 + (hop + 1) * 16 + t;
            asm volatile("red.global.add.v4.f32 [%0], {%1, %2, %3, %4};"
                         :: "l"(d), "f"(a[i].x * v), "f"(a[i].y * v),
                            "f"(a[i].z * v), "f"(a[i].w * v)
                         : "memory");
        }
    }
}

// ---------------------------------------------------------------------------
// Kernel 3 (per hop): message dropout in place on out slice hop+1.
// 8 elements (2 float4) per thread.  Last hop also re-zeroes g_cnt.
// ---------------------------------------------------------------------------
__global__ void k_drop(float4* __restrict__ out, int hop, int clear_cnt,
                       uint32_t k0, uint32_t k1, uint32_t one)
{
    int t = blockIdx.x * blockDim.x + threadIdx.x;   // over ND/8 = 1.2M
    if (t >= ND / 8) return;
    if (clear_cnt && t < 4) g_cnt[t] = 0;   // for next call/replay

    int n   = t >> 3;
    int sub = t & 7;
    uint32_t ks2 = k0 ^ k1 ^ 0x1BD11BDAu;
    uint32_t j = (uint32_t)n * 64u + (uint32_t)sub * 8u;

    uint32_t b[8];
#pragma unroll
    for (int i = 0; i < 8; i++) b[i] = tf_bits_i(k0, k1, ks2, j + (uint32_t)i, one);

    size_t o = (size_t)n * 64 + (size_t)(hop + 1) * 16 + sub * 2;
    float4 a0 = out[o];
    float4 a1 = out[o + 1];
    const float s = 1.0f / 0.9f;
    float4 r0, r1;
    r0.x = (b[0] < MSG_TH) ? a0.x * s : 0.0f;
    r0.y = (b[1] < MSG_TH) ? a0.y * s : 0.0f;
    r0.z = (b[2] < MSG_TH) ? a0.z * s : 0.0f;
    r0.w = (b[3] < MSG_TH) ? a0.w * s : 0.0f;
    r1.x = (b[4] < MSG_TH) ? a1.x * s : 0.0f;
    r1.y = (b[5] < MSG_TH) ? a1.y * s : 0.0f;
    r1.z = (b[6] < MSG_TH) ? a1.z * s : 0.0f;
    r1.w = (b[7] < MSG_TH) ? a1.w * s : 0.0f;
    out[o]     = r0;
    out[o + 1] = r1;
}

// ---------------------------------------------------------------------------
// Launch
// ---------------------------------------------------------------------------
extern "C" void kernel_launch(void* const* d_in, const int* in_sizes, int n_in,
                              void* d_out, int out_size)
{
    const float4* ue   = (const float4*)d_in[0];
    const float4* ie   = (const float4*)d_in[1];
    const int4*   rows = (const int4*)d_in[2];
    const int4*   cols = (const int4*)d_in[3];
    const float4* vals = (const float4*)d_in[4];
    float4*       out  = (float4*)d_out;

    // Partitionable ("fold-like") split: split(key,3)[i] = threefry(key, (0,i))
    uint32_t key0 = 0u, key1 = 42u;   // jax.random.key(42)
    uint32_t ke[N_HOPS][2], km[N_HOPS][2];
    for (int h = 0; h < N_HOPS; h++) {
        uint32_t n0, n1;
        threefry2x32_host(key0, key1, 0u, 0u, n0, n1);
        threefry2x32_host(key0, key1, 0u, 1u, ke[h][0], ke[h][1]);
        threefry2x32_host(key0, key1, 0u, 2u, km[h][0], km[h][1]);
        key0 = n0; key1 = n1;
    }

    const int B = 256;
    const uint32_t one = 1u;   // runtime-opaque multiplier for IMAD adds

    k_init_edge<<<NB_INIT + NB_EDGE, B>>>(ue, ie, out,
                                          vals, rows, cols,
                                          ke[0][0], ke[0][1],
                                          ke[1][0], ke[1][1],
                                          ke[2][0], ke[2][1], one);

    for (int h = 0; h < N_HOPS; h++) {
        k_spmm<<<NB_SPMM, B>>>(out, h);
        int cc = (h + 1 == N_HOPS) ? 1 : 0;
        k_drop<<<NB_DROP, B>>>(out, h, cc, km[h][0], km[h][1], one);
    }
}

// round 8
// speedup vs baseline: 1.6699x; 1.0396x over previous
#include <cuda_runtime.h>
#include <cstdint>

#define N_USERS 50000
#define N_ITEMS 100000
#define N_NODES 150000
#define NNZ     1000000
#define D       64
#define ND      (N_NODES * D)      /* 9,600,000 */
#define N_HOPS  3

// keep message iff bits < 0xE6666600  (== u01(bits) < 0.9f exactly)
#define MSG_TH  0xE6666600u

#define NB_INIT 9375               /* ND/4/256 exact */
#define NB_EDGE 977                /* ceil(NNZ/4 / 256) */
#define EPG     4                  /* edges per 16-thread group in spmm */
#define CAP_EDGES 540672           /* kept-edge cap (expected 500k, ~80 sigma) */
#define NB_SPMM ((CAP_EDGES / EPG) * 16 / 256)   /* 8448 blocks */
#define NB_DROP 4688               /* ceil(1,200,000 / 256) */

// Scratch (no cudaMalloc allowed)
__device__ int4 g_edges[N_HOPS][NNZ];   // compacted kept edges {row, col, valbits, 0}
__device__ int  g_cnt[4];               // per-hop kept-edge counters (0 at module
                                        // load; last k_drop re-zeroes -> replay-safe)

// ---------------------------------------------------------------------------
// JAX threefry2x32.  Host version (key derivation) + device version with adds
// on the fma pipe (IMAD via runtime-opaque multiplier `one`).
// ---------------------------------------------------------------------------
__host__ __forceinline__ uint32_t rotl32h(uint32_t x, int r) {
    return (x << r) | (x >> (32 - r));
}

__host__ void threefry2x32_host(uint32_t k0, uint32_t k1, uint32_t x0, uint32_t x1,
                                uint32_t& o0, uint32_t& o1)
{
    uint32_t ks2 = k0 ^ k1 ^ 0x1BD11BDAu;
    x0 += k0; x1 += k1;
#define TF_R4(a,b,c,d)                                   \
    x0 += x1; x1 = rotl32h(x1,(a)); x1 ^= x0;            \
    x0 += x1; x1 = rotl32h(x1,(b)); x1 ^= x0;            \
    x0 += x1; x1 = rotl32h(x1,(c)); x1 ^= x0;            \
    x0 += x1; x1 = rotl32h(x1,(d)); x1 ^= x0;
    TF_R4(13,15,26,6);   x0 += k1;  x1 += ks2 + 1u;
    TF_R4(17,29,16,24);  x0 += ks2; x1 += k0  + 2u;
    TF_R4(13,15,26,6);   x0 += k0;  x1 += k1  + 3u;
    TF_R4(17,29,16,24);  x0 += k1;  x1 += ks2 + 4u;
    TF_R4(13,15,26,6);   x0 += ks2; x1 += k0  + 5u;
#undef TF_R4
    o0 = x0; o1 = x1;
}

__device__ __forceinline__ uint32_t addi(uint32_t a, uint32_t b, uint32_t one) {
    uint32_t d;
    asm("mad.lo.u32 %0, %1, %2, %3;" : "=r"(d) : "r"(a), "r"(one), "r"(b));
    return d;
}

__device__ __forceinline__ uint32_t rotxor(uint32_t x, int r, uint32_t y) {
    return __funnelshift_l(x, x, (unsigned)r) ^ y;
}

__device__ __forceinline__ void tf_round4(uint32_t& x0, uint32_t& x1,
                                          int a, int b, int c, int d,
                                          uint32_t one)
{
    x0 = addi(x0, x1, one); x1 = rotxor(x1, a, x0);
    x0 = addi(x0, x1, one); x1 = rotxor(x1, b, x0);
    x0 = addi(x0, x1, one); x1 = rotxor(x1, c, x0);
    x0 = addi(x0, x1, one); x1 = rotxor(x1, d, x0);
}

// Partitionable-mode random bits at flat index i: block (0, i), bits = o0^o1.
__device__ __forceinline__ uint32_t tf_bits_i(uint32_t k0, uint32_t k1,
                                              uint32_t ks2, uint32_t i,
                                              uint32_t one)
{
    uint32_t x0 = k0;                 // 0 + k0
    uint32_t x1 = addi(i, k1, one);
    tf_round4(x0, x1, 13, 15, 26,  6, one);
    x0 = addi(x0, k1,  one); x1 = addi(x1, ks2 + 1u, one);
    tf_round4(x0, x1, 17, 29, 16, 24, one);
    x0 = addi(x0, ks2, one); x1 = addi(x1, k0  + 2u, one);
    tf_round4(x0, x1, 13, 15, 26,  6, one);
    x0 = addi(x0, k0,  one); x1 = addi(x1, k1  + 3u, one);
    tf_round4(x0, x1, 17, 29, 16, 24, one);
    x0 = addi(x0, k1,  one); x1 = addi(x1, ks2 + 4u, one);
    tf_round4(x0, x1, 13, 15, 26,  6, one);
    x0 = addi(x0, ks2, one); x1 = addi(x1, k0  + 5u, one);
    return x0 ^ x1;
}

// ---------------------------------------------------------------------------
// Kernel 1: init out (slice0 = embeddings, slices 1-3 = 0) + edge dropout
// with compaction for all 3 hops.  Disjoint block ranges.
// ---------------------------------------------------------------------------
__global__ void k_init_edge(const float4* __restrict__ ue,
                            const float4* __restrict__ ie,
                            float4* __restrict__ out,
                            const float4* __restrict__ vals,
                            const int4*  __restrict__ rows,
                            const int4*  __restrict__ cols,
                            uint32_t ke00, uint32_t ke01,
                            uint32_t ke10, uint32_t ke11,
                            uint32_t ke20, uint32_t ke21,
                            uint32_t one)
{
    int blk = blockIdx.x;
    if (blk < NB_INIT) {
        // out[node][0][*] <- embed; out[node][1..3][*] <- 0
        int i = blk * blockDim.x + threadIdx.x;   // over ND/4, exact
        int node = i >> 4;
        int q    = i & 15;
        float4 v = (node < N_USERS) ? ue[node * 16 + q]
                                    : ie[(node - N_USERS) * 16 + q];
        unsigned o = (unsigned)node * 64u + (unsigned)q;
        float4 z = make_float4(0.f, 0.f, 0.f, 0.f);
        out[o]      = v;
        out[o + 16] = z;
        out[o + 32] = z;
        out[o + 48] = z;
        return;
    }

    // edge dropout + compaction, 4 edges/thread, all 3 hops
    int t    = (blk - NB_INIT) * blockDim.x + threadIdx.x;
    int lane = threadIdx.x & 31;
    bool live = (t < NNZ / 4);

    float4 v  = make_float4(0.f, 0.f, 0.f, 0.f);
    int4   rr = make_int4(0, 0, 0, 0), cc = make_int4(0, 0, 0, 0);
    if (live) { v = vals[t]; rr = rows[t]; cc = cols[t]; }
    float vv[4] = {v.x, v.y, v.z, v.w};
    int   ra[4] = {rr.x, rr.y, rr.z, rr.w};
    int   ca[4] = {cc.x, cc.y, cc.z, cc.w};
    uint32_t j  = (uint32_t)t * 4u;

    uint32_t K0[3] = {ke00, ke10, ke20};
    uint32_t K1[3] = {ke01, ke11, ke21};

#pragma unroll
    for (int h = 0; h < N_HOPS; h++) {
        uint32_t ks2 = K0[h] ^ K1[h] ^ 0x1BD11BDAu;
        int4 e[4];
        int kept = 0;
        if (live) {
#pragma unroll
            for (int i = 0; i < 4; i++) {
                uint32_t b = tf_bits_i(K0[h], K1[h], ks2, j + (uint32_t)i, one);
                if ((int)b < 0) {                     // keep: u >= 0.5
                    e[kept] = make_int4(ra[i], ca[i],
                                        __float_as_int(vv[i] * 2.0f), 0);
                    kept++;
                }
            }
        }
        // warp inclusive scan of kept
        int off = kept;
#pragma unroll
        for (int d = 1; d < 32; d <<= 1) {
            int nn = __shfl_up_sync(0xFFFFFFFFu, off, d);
            if (lane >= d) off += nn;
        }
        int total = __shfl_sync(0xFFFFFFFFu, off, 31);
        int base  = 0;
        if (lane == 31 && total > 0) base = atomicAdd(&g_cnt[h], total);
        base = __shfl_sync(0xFFFFFFFFu, base, 31);

        int pos = base + off - kept;
#pragma unroll
        for (int i = 0; i < 4; i++)
            if (i < kept) g_edges[h][pos + i] = e[i];
    }
}

// ---------------------------------------------------------------------------
// Kernel 2 (per hop): SpMM scatter over compacted edges, directly on out.
// 16 threads per group of EPG=4 edges: batched meta loads -> 4 independent
// gathers (slice hop) -> 4 vector reds (slice hop+1).  32-bit indexing;
// launch_bounds keeps regs low for occupancy (latency-bound kernel).
// ---------------------------------------------------------------------------
__global__ void __launch_bounds__(256, 6)
k_spmm(float4* __restrict__ out, int hop, unsigned src_off, unsigned dst_off)
{
    unsigned g  = blockIdx.x * blockDim.x + threadIdx.x;
    int      eg = (int)(g >> 4);
    unsigned t  = g & 15u;
    int count = g_cnt[hop];
    int base  = eg * EPG;
    if (base >= count) return;
    int n = count - base; if (n > EPG) n = EPG;

    const int4* E = g_edges[hop];
    int4 m[EPG];
#pragma unroll
    for (int i = 0; i < EPG; i++)
        if (i < n) m[i] = E[base + i];

    float4 a[EPG];
#pragma unroll
    for (int i = 0; i < EPG; i++)
        if (i < n) a[i] = out[(unsigned)m[i].y * 64u + src_off + t];

#pragma unroll
    for (int i = 0; i < EPG; i++) {
        if (i < n) {
            float v = __int_as_float(m[i].z);
            float4* d = out + ((unsigned)m[i].x * 64u + dst_off + t);
            asm volatile("red.global.add.v4.f32 [%0], {%1, %2, %3, %4};"
                         :: "l"(d), "f"(a[i].x * v), "f"(a[i].y * v),
                            "f"(a[i].z * v), "f"(a[i].w * v)
                         : "memory");
        }
    }
}

// ---------------------------------------------------------------------------
// Kernel 3 (per hop): message dropout in place on out slice hop+1.
// 8 elements (2 float4) per thread.  Last hop also re-zeroes g_cnt.
// ---------------------------------------------------------------------------
__global__ void k_drop(float4* __restrict__ out, unsigned dst_off, int clear_cnt,
                       uint32_t k0, uint32_t k1, uint32_t one)
{
    int t = blockIdx.x * blockDim.x + threadIdx.x;   // over ND/8 = 1.2M
    if (t >= ND / 8) return;
    if (clear_cnt && t < 4) g_cnt[t] = 0;   // for next call/replay

    unsigned n   = (unsigned)t >> 3;
    unsigned sub = (unsigned)t & 7u;
    uint32_t ks2 = k0 ^ k1 ^ 0x1BD11BDAu;
    uint32_t j = n * 64u + sub * 8u;

    uint32_t b[8];
#pragma unroll
    for (int i = 0; i < 8; i++) b[i] = tf_bits_i(k0, k1, ks2, j + (uint32_t)i, one);

    unsigned o = n * 64u + dst_off + sub * 2u;
    float4 a0 = out[o];
    float4 a1 = out[o + 1];
    const float s = 1.0f / 0.9f;
    float4 r0, r1;
    r0.x = (b[0] < MSG_TH) ? a0.x * s : 0.0f;
    r0.y = (b[1] < MSG_TH) ? a0.y * s : 0.0f;
    r0.z = (b[2] < MSG_TH) ? a0.z * s : 0.0f;
    r0.w = (b[3] < MSG_TH) ? a0.w * s : 0.0f;
    r1.x = (b[4] < MSG_TH) ? a1.x * s : 0.0f;
    r1.y = (b[5] < MSG_TH) ? a1.y * s : 0.0f;
    r1.z = (b[6] < MSG_TH) ? a1.z * s : 0.0f;
    r1.w = (b[7] < MSG_TH) ? a1.w * s : 0.0f;
    out[o]     = r0;
    out[o + 1] = r1;
}

// ---------------------------------------------------------------------------
// Launch
// ---------------------------------------------------------------------------
extern "C" void kernel_launch(void* const* d_in, const int* in_sizes, int n_in,
                              void* d_out, int out_size)
{
    const float4* ue   = (const float4*)d_in[0];
    const float4* ie   = (const float4*)d_in[1];
    const int4*   rows = (const int4*)d_in[2];
    const int4*   cols = (const int4*)d_in[3];
    const float4* vals = (const float4*)d_in[4];
    float4*       out  = (float4*)d_out;

    // Partitionable ("fold-like") split: split(key,3)[i] = threefry(key, (0,i))
    uint32_t key0 = 0u, key1 = 42u;   // jax.random.key(42)
    uint32_t ke[N_HOPS][2], km[N_HOPS][2];
    for (int h = 0; h < N_HOPS; h++) {
        uint32_t n0, n1;
        threefry2x32_host(key0, key1, 0u, 0u, n0, n1);
        threefry2x32_host(key0, key1, 0u, 1u, ke[h][0], ke[h][1]);
        threefry2x32_host(key0, key1, 0u, 2u, km[h][0], km[h][1]);
        key0 = n0; key1 = n1;
    }

    const int B = 256;
    const uint32_t one = 1u;   // runtime-opaque multiplier for IMAD adds

    k_init_edge<<<NB_INIT + NB_EDGE, B>>>(ue, ie, out,
                                          vals, rows, cols,
                                          ke[0][0], ke[0][1],
                                          ke[1][0], ke[1][1],
                                          ke[2][0], ke[2][1], one);

    for (int h = 0; h < N_HOPS; h++) {
        unsigned src_off = (unsigned)h * 16u;
        unsigned dst_off = (unsigned)(h + 1) * 16u;
        k_spmm<<<NB_SPMM, B>>>(out, h, src_off, dst_off);
        int cc = (h + 1 == N_HOPS) ? 1 : 0;
        k_drop<<<NB_DROP, B>>>(out, dst_off, cc, km[h][0], km[h][1], one);
    }
}

// round 9
// speedup vs baseline: 1.7263x; 1.0337x over previous
#include <cuda_runtime.h>
#include <cstdint>

#define N_USERS 50000
#define N_ITEMS 100000
#define N_NODES 150000
#define NNZ     1000000
#define D       64
#define ND      (N_NODES * D)      /* 9,600,000 */
#define N_HOPS  3

// keep message iff bits < 0xE6666600  (== u01(bits) < 0.9f exactly)
#define MSG_TH  0xE6666600u

#define NB_INIT 9375               /* ND/4/256 exact */
#define NB_EDGE 977                /* ceil(NNZ/4 / 256) */
#define EPG     4                  /* edges per 16-thread group in spmm */
#define CAP_EDGES 540672           /* kept-edge cap (expected 500k, ~80 sigma) */
#define NB_SPMM ((CAP_EDGES / EPG) * 16 / 256)   /* 8448 blocks */
#define NB_DROP 4688               /* ceil(1,200,000 / 256) */

// Scratch (no cudaMalloc allowed)
__device__ int4 g_edges[N_HOPS][NNZ];   // compacted kept edges {row, col, valbits, 0}
__device__ int  g_cnt[4];               // per-hop kept-edge counters (0 at module
                                        // load; last k_drop re-zeroes -> replay-safe)

// ---------------------------------------------------------------------------
// JAX threefry2x32.  Host version (key derivation) + device version with adds
// on the fma pipe (IMAD via runtime-opaque multiplier `one`).
// ---------------------------------------------------------------------------
__host__ __forceinline__ uint32_t rotl32h(uint32_t x, int r) {
    return (x << r) | (x >> (32 - r));
}

__host__ void threefry2x32_host(uint32_t k0, uint32_t k1, uint32_t x0, uint32_t x1,
                                uint32_t& o0, uint32_t& o1)
{
    uint32_t ks2 = k0 ^ k1 ^ 0x1BD11BDAu;
    x0 += k0; x1 += k1;
#define TF_R4(a,b,c,d)                                   \
    x0 += x1; x1 = rotl32h(x1,(a)); x1 ^= x0;            \
    x0 += x1; x1 = rotl32h(x1,(b)); x1 ^= x0;            \
    x0 += x1; x1 = rotl32h(x1,(c)); x1 ^= x0;            \
    x0 += x1; x1 = rotl32h(x1,(d)); x1 ^= x0;
    TF_R4(13,15,26,6);   x0 += k1;  x1 += ks2 + 1u;
    TF_R4(17,29,16,24);  x0 += ks2; x1 += k0  + 2u;
    TF_R4(13,15,26,6);   x0 += k0;  x1 += k1  + 3u;
    TF_R4(17,29,16,24);  x0 += k1;  x1 += ks2 + 4u;
    TF_R4(13,15,26,6);   x0 += ks2; x1 += k0  + 5u;
#undef TF_R4
    o0 = x0; o1 = x1;
}

__device__ __forceinline__ uint32_t addi(uint32_t a, uint32_t b, uint32_t one) {
    uint32_t d;
    asm("mad.lo.u32 %0, %1, %2, %3;" : "=r"(d) : "r"(a), "r"(one), "r"(b));
    return d;
}

__device__ __forceinline__ uint32_t rotxor(uint32_t x, int r, uint32_t y) {
    return __funnelshift_l(x, x, (unsigned)r) ^ y;
}

__device__ __forceinline__ void tf_round4(uint32_t& x0, uint32_t& x1,
                                          int a, int b, int c, int d,
                                          uint32_t one)
{
    x0 = addi(x0, x1, one); x1 = rotxor(x1, a, x0);
    x0 = addi(x0, x1, one); x1 = rotxor(x1, b, x0);
    x0 = addi(x0, x1, one); x1 = rotxor(x1, c, x0);
    x0 = addi(x0, x1, one); x1 = rotxor(x1, d, x0);
}

// Partitionable-mode random bits at flat index i: block (0, i), bits = o0^o1.
__device__ __forceinline__ uint32_t tf_bits_i(uint32_t k0, uint32_t k1,
                                              uint32_t ks2, uint32_t i,
                                              uint32_t one)
{
    uint32_t x0 = k0;                 // 0 + k0
    uint32_t x1 = addi(i, k1, one);
    tf_round4(x0, x1, 13, 15, 26,  6, one);
    x0 = addi(x0, k1,  one); x1 = addi(x1, ks2 + 1u, one);
    tf_round4(x0, x1, 17, 29, 16, 24, one);
    x0 = addi(x0, ks2, one); x1 = addi(x1, k0  + 2u, one);
    tf_round4(x0, x1, 13, 15, 26,  6, one);
    x0 = addi(x0, k0,  one); x1 = addi(x1, k1  + 3u, one);
    tf_round4(x0, x1, 17, 29, 16, 24, one);
    x0 = addi(x0, k1,  one); x1 = addi(x1, ks2 + 4u, one);
    tf_round4(x0, x1, 13, 15, 26,  6, one);
    x0 = addi(x0, ks2, one); x1 = addi(x1, k0  + 5u, one);
    return x0 ^ x1;
}

// ---------------------------------------------------------------------------
// Kernel 1: init out (slice0 = embeddings, slice1 = 0) + edge dropout with
// compaction for all 3 hops.  Slices 2,3 are zeroed later by drop0/drop1
// (before their respective spmm consumers).  Disjoint block ranges.
// ---------------------------------------------------------------------------
__global__ void k_init_edge(const float4* __restrict__ ue,
                            const float4* __restrict__ ie,
                            float4* __restrict__ out,
                            const float4* __restrict__ vals,
                            const int4*  __restrict__ rows,
                            const int4*  __restrict__ cols,
                            uint32_t ke00, uint32_t ke01,
                            uint32_t ke10, uint32_t ke11,
                            uint32_t ke20, uint32_t ke21,
                            uint32_t one)
{
    int blk = blockIdx.x;
    if (blk < NB_INIT) {
        // out[node][0][*] <- embed; out[node][1][*] <- 0
        int i = blk * blockDim.x + threadIdx.x;   // over ND/4, exact
        int node = i >> 4;
        int q    = i & 15;
        float4 v = (node < N_USERS) ? ue[node * 16 + q]
                                    : ie[(node - N_USERS) * 16 + q];
        unsigned o = (unsigned)node * 64u + (unsigned)q;
        out[o]      = v;
        out[o + 16] = make_float4(0.f, 0.f, 0.f, 0.f);
        return;
    }

    // edge dropout + compaction, 4 edges/thread, all 3 hops
    int t    = (blk - NB_INIT) * blockDim.x + threadIdx.x;
    int lane = threadIdx.x & 31;
    bool live = (t < NNZ / 4);

    float4 v  = make_float4(0.f, 0.f, 0.f, 0.f);
    int4   rr = make_int4(0, 0, 0, 0), cc = make_int4(0, 0, 0, 0);
    if (live) { v = vals[t]; rr = rows[t]; cc = cols[t]; }
    float vv[4] = {v.x, v.y, v.z, v.w};
    int   ra[4] = {rr.x, rr.y, rr.z, rr.w};
    int   ca[4] = {cc.x, cc.y, cc.z, cc.w};
    uint32_t j  = (uint32_t)t * 4u;

    uint32_t K0[3] = {ke00, ke10, ke20};
    uint32_t K1[3] = {ke01, ke11, ke21};

#pragma unroll
    for (int h = 0; h < N_HOPS; h++) {
        uint32_t ks2 = K0[h] ^ K1[h] ^ 0x1BD11BDAu;
        int4 e[4];
        int kept = 0;
        if (live) {
#pragma unroll
            for (int i = 0; i < 4; i++) {
                uint32_t b = tf_bits_i(K0[h], K1[h], ks2, j + (uint32_t)i, one);
                if ((int)b < 0) {                     // keep: u >= 0.5
                    e[kept] = make_int4(ra[i], ca[i],
                                        __float_as_int(vv[i] * 2.0f), 0);
                    kept++;
                }
            }
        }
        // warp inclusive scan of kept
        int off = kept;
#pragma unroll
        for (int d = 1; d < 32; d <<= 1) {
            int nn = __shfl_up_sync(0xFFFFFFFFu, off, d);
            if (lane >= d) off += nn;
        }
        int total = __shfl_sync(0xFFFFFFFFu, off, 31);
        int base  = 0;
        if (lane == 31 && total > 0) base = atomicAdd(&g_cnt[h], total);
        base = __shfl_sync(0xFFFFFFFFu, base, 31);

        int pos = base + off - kept;
#pragma unroll
        for (int i = 0; i < 4; i++)
            if (i < kept) g_edges[h][pos + i] = e[i];
    }
}

// ---------------------------------------------------------------------------
// Kernel 2 (per hop): SpMM scatter over compacted edges, directly on out.
// 16 threads per group of EPG=4 edges.  Hop 0 gathers straight from ue/ie
// (decouples from init's slice-0 stores); hops 1-2 gather out slice hop.
// ---------------------------------------------------------------------------
__global__ void __launch_bounds__(256, 6)
k_spmm(float4* __restrict__ out,
       const float4* __restrict__ ue, const float4* __restrict__ ie,
       int hop, unsigned src_off, unsigned dst_off)
{
    unsigned g  = blockIdx.x * blockDim.x + threadIdx.x;
    int      eg = (int)(g >> 4);
    unsigned t  = g & 15u;
    int count = g_cnt[hop];
    int base  = eg * EPG;
    if (base >= count) return;
    int n = count - base; if (n > EPG) n = EPG;

    const int4* E = g_edges[hop];
    int4 m[EPG];
#pragma unroll
    for (int i = 0; i < EPG; i++)
        if (i < n) m[i] = E[base + i];

    float4 a[EPG];
#pragma unroll
    for (int i = 0; i < EPG; i++) {
        if (i < n) {
            unsigned c = (unsigned)m[i].y;
            const float4* p;
            if (hop == 0)
                p = (c < N_USERS) ? (ue + c * 16u)
                                  : (ie + (c - N_USERS) * 16u);
            else
                p = out + (c * 64u + src_off);
            a[i] = p[t];
        }
    }

#pragma unroll
    for (int i = 0; i < EPG; i++) {
        if (i < n) {
            float v = __int_as_float(m[i].z);
            float4* d = out + ((unsigned)m[i].x * 64u + dst_off + t);
            asm volatile("red.global.add.v4.f32 [%0], {%1, %2, %3, %4};"
                         :: "l"(d), "f"(a[i].x * v), "f"(a[i].y * v),
                            "f"(a[i].z * v), "f"(a[i].w * v)
                         : "memory");
        }
    }
}

// ---------------------------------------------------------------------------
// Kernel 3 (per hop): message dropout in place on out slice hop+1, plus
// deferred zeroing of slice hop+2 (consumed by the NEXT spmm) while the
// cipher keeps the ALU pipes busy.  Last hop re-zeroes g_cnt instead.
// ---------------------------------------------------------------------------
__global__ void k_drop(float4* __restrict__ out, unsigned dst_off,
                       unsigned zero_off /* 0 = none */, int clear_cnt,
                       uint32_t k0, uint32_t k1, uint32_t one)
{
    int t = blockIdx.x * blockDim.x + threadIdx.x;   // over ND/8 = 1.2M
    if (t >= ND / 8) return;
    if (clear_cnt && t < 4) g_cnt[t] = 0;   // for next call/replay

    unsigned n   = (unsigned)t >> 3;
    unsigned sub = (unsigned)t & 7u;
    uint32_t ks2 = k0 ^ k1 ^ 0x1BD11BDAu;
    uint32_t j = n * 64u + sub * 8u;

    uint32_t b[8];
#pragma unroll
    for (int i = 0; i < 8; i++) b[i] = tf_bits_i(k0, k1, ks2, j + (uint32_t)i, one);

    unsigned o = n * 64u + dst_off + sub * 2u;
    float4 a0 = out[o];
    float4 a1 = out[o + 1];

    if (zero_off) {
        unsigned z = n * 64u + zero_off + sub * 2u;
        float4 zv = make_float4(0.f, 0.f, 0.f, 0.f);
        out[z]     = zv;
        out[z + 1] = zv;
    }

    const float s = 1.0f / 0.9f;
    float4 r0, r1;
    r0.x = (b[0] < MSG_TH) ? a0.x * s : 0.0f;
    r0.y = (b[1] < MSG_TH) ? a0.y * s : 0.0f;
    r0.z = (b[2] < MSG_TH) ? a0.z * s : 0.0f;
    r0.w = (b[3] < MSG_TH) ? a0.w * s : 0.0f;
    r1.x = (b[4] < MSG_TH) ? a1.x * s : 0.0f;
    r1.y = (b[5] < MSG_TH) ? a1.y * s : 0.0f;
    r1.z = (b[6] < MSG_TH) ? a1.z * s : 0.0f;
    r1.w = (b[7] < MSG_TH) ? a1.w * s : 0.0f;
    out[o]     = r0;
    out[o + 1] = r1;
}

// ---------------------------------------------------------------------------
// Launch
// ---------------------------------------------------------------------------
extern "C" void kernel_launch(void* const* d_in, const int* in_sizes, int n_in,
                              void* d_out, int out_size)
{
    const float4* ue   = (const float4*)d_in[0];
    const float4* ie   = (const float4*)d_in[1];
    const int4*   rows = (const int4*)d_in[2];
    const int4*   cols = (const int4*)d_in[3];
    const float4* vals = (const float4*)d_in[4];
    float4*       out  = (float4*)d_out;

    // Partitionable ("fold-like") split: split(key,3)[i] = threefry(key, (0,i))
    uint32_t key0 = 0u, key1 = 42u;   // jax.random.key(42)
    uint32_t ke[N_HOPS][2], km[N_HOPS][2];
    for (int h = 0; h < N_HOPS; h++) {
        uint32_t n0, n1;
        threefry2x32_host(key0, key1, 0u, 0u, n0, n1);
        threefry2x32_host(key0, key1, 0u, 1u, ke[h][0], ke[h][1]);
        threefry2x32_host(key0, key1, 0u, 2u, km[h][0], km[h][1]);
        key0 = n0; key1 = n1;
    }

    const int B = 256;
    const uint32_t one = 1u;   // runtime-opaque multiplier for IMAD adds

    k_init_edge<<<NB_INIT + NB_EDGE, B>>>(ue, ie, out,
                                          vals, rows, cols,
                                          ke[0][0], ke[0][1],
                                          ke[1][0], ke[1][1],
                                          ke[2][0], ke[2][1], one);

    for (int h = 0; h < N_HOPS; h++) {
        unsigned src_off = (unsigned)h * 16u;
        unsigned dst_off = (unsigned)(h + 1) * 16u;
        k_spmm<<<NB_SPMM, B>>>(out, ue, ie, h, src_off, dst_off);
        // drop0 zeroes slice2 (for spmm1); drop1 zeroes slice3 (for spmm2)
        unsigned zoff = (h + 2 <= N_HOPS) ? (unsigned)(h + 2) * 16u : 0u;
        int cc = (h + 1 == N_HOPS) ? 1 : 0;
        k_drop<<<NB_DROP, B>>>(out, dst_off, zoff, cc, km[h][0], km[h][1], one);
    }
}

// round 10
// speedup vs baseline: 1.9451x; 1.1267x over previous
#include <cuda_runtime.h>
#include <cstdint>

#define N_USERS 50000
#define N_ITEMS 100000
#define N_NODES 150000
#define NNZ     1000000
#define D       64
#define ND      (N_NODES * D)      /* 9,600,000 */
#define N_HOPS  3

// keep message iff bits < 0xE6666600  (== u01(bits) < 0.9f exactly)
#define MSG_TH  0xE6666600u

#define NB_INIT 9375               /* ND/4/256 exact */
#define NB_EDGE 977                /* ceil(NNZ/4 / 256) */
#define NB_MASK 4688               /* ceil(ND/8 / 256) */
#define NB_A    (NB_INIT + NB_EDGE + NB_MASK)   /* 15040 */
#define EPG     4                  /* edges per 16-thread group in spmm */
#define CAP_EDGES 540672           /* kept-edge cap (expected 500k, ~80 sigma) */
#define NB_SPMM ((CAP_EDGES / EPG) * 16 / 256)  /* 8448 */
#define NB_B    (NB_SPMM + NB_MASK)             /* 13136 */

// Scratch (no cudaMalloc allowed)
__device__ int4    g_edges[N_HOPS][NNZ]; // compacted kept edges {row,col,valbits,0}
__device__ uint8_t g_mask[N_HOPS][ND];   // per-element keep mask (1 byte each)
__device__ int     g_cnt[4];             // kept-edge counters (0 at module load;
                                         // k_tail re-zeroes -> replay-safe)

// ---------------------------------------------------------------------------
// JAX threefry2x32.  Host version (key derivation) + device version with adds
// on the fma pipe (IMAD via runtime-opaque multiplier `one`).
// ---------------------------------------------------------------------------
__host__ __forceinline__ uint32_t rotl32h(uint32_t x, int r) {
    return (x << r) | (x >> (32 - r));
}

__host__ void threefry2x32_host(uint32_t k0, uint32_t k1, uint32_t x0, uint32_t x1,
                                uint32_t& o0, uint32_t& o1)
{
    uint32_t ks2 = k0 ^ k1 ^ 0x1BD11BDAu;
    x0 += k0; x1 += k1;
#define TF_R4(a,b,c,d)                                   \
    x0 += x1; x1 = rotl32h(x1,(a)); x1 ^= x0;            \
    x0 += x1; x1 = rotl32h(x1,(b)); x1 ^= x0;            \
    x0 += x1; x1 = rotl32h(x1,(c)); x1 ^= x0;            \
    x0 += x1; x1 = rotl32h(x1,(d)); x1 ^= x0;
    TF_R4(13,15,26,6);   x0 += k1;  x1 += ks2 + 1u;
    TF_R4(17,29,16,24);  x0 += ks2; x1 += k0  + 2u;
    TF_R4(13,15,26,6);   x0 += k0;  x1 += k1  + 3u;
    TF_R4(17,29,16,24);  x0 += k1;  x1 += ks2 + 4u;
    TF_R4(13,15,26,6);   x0 += ks2; x1 += k0  + 5u;
#undef TF_R4
    o0 = x0; o1 = x1;
}

__device__ __forceinline__ uint32_t addi(uint32_t a, uint32_t b, uint32_t one) {
    uint32_t d;
    asm("mad.lo.u32 %0, %1, %2, %3;" : "=r"(d) : "r"(a), "r"(one), "r"(b));
    return d;
}

__device__ __forceinline__ uint32_t rotxor(uint32_t x, int r, uint32_t y) {
    return __funnelshift_l(x, x, (unsigned)r) ^ y;
}

__device__ __forceinline__ void tf_round4(uint32_t& x0, uint32_t& x1,
                                          int a, int b, int c, int d,
                                          uint32_t one)
{
    x0 = addi(x0, x1, one); x1 = rotxor(x1, a, x0);
    x0 = addi(x0, x1, one); x1 = rotxor(x1, b, x0);
    x0 = addi(x0, x1, one); x1 = rotxor(x1, c, x0);
    x0 = addi(x0, x1, one); x1 = rotxor(x1, d, x0);
}

// Partitionable-mode random bits at flat index i: block (0, i), bits = o0^o1.
__device__ __forceinline__ uint32_t tf_bits_i(uint32_t k0, uint32_t k1,
                                              uint32_t ks2, uint32_t i,
                                              uint32_t one)
{
    uint32_t x0 = k0;                 // 0 + k0
    uint32_t x1 = addi(i, k1, one);
    tf_round4(x0, x1, 13, 15, 26,  6, one);
    x0 = addi(x0, k1,  one); x1 = addi(x1, ks2 + 1u, one);
    tf_round4(x0, x1, 17, 29, 16, 24, one);
    x0 = addi(x0, ks2, one); x1 = addi(x1, k0  + 2u, one);
    tf_round4(x0, x1, 13, 15, 26,  6, one);
    x0 = addi(x0, k0,  one); x1 = addi(x1, k1  + 3u, one);
    tf_round4(x0, x1, 17, 29, 16, 24, one);
    x0 = addi(x0, k1,  one); x1 = addi(x1, ks2 + 4u, one);
    tf_round4(x0, x1, 13, 15, 26,  6, one);
    x0 = addi(x0, ks2, one); x1 = addi(x1, k0  + 5u, one);
    return x0 ^ x1;
}

// ---------------------------------------------------------------------------
// Maskgen block body: thread t covers elements [t*8, t*8+8): 8 ciphers ->
// 8 mask bytes packed in one 64-bit store.  Optionally zeroes the out slice
// at zero_off (deferred zeroing for a later spmm's destination).
// ---------------------------------------------------------------------------
__device__ __forceinline__ void maskgen_body(int t, uint8_t* __restrict__ mp,
                                             float4* __restrict__ out,
                                             unsigned zero_off,
                                             uint32_t k0, uint32_t k1,
                                             uint32_t one)
{
    if (t >= ND / 8) return;
    uint32_t ks2 = k0 ^ k1 ^ 0x1BD11BDAu;
    uint32_t j = (uint32_t)t * 8u;

    unsigned long long pack = 0ull;
#pragma unroll
    for (int i = 0; i < 8; i++) {
        uint32_t b = tf_bits_i(k0, k1, ks2, j + (uint32_t)i, one);
        pack |= (unsigned long long)(b < MSG_TH ? 1u : 0u) << (i * 8);
    }
    *(unsigned long long*)(mp + j) = pack;

    if (zero_off) {
        unsigned n = j >> 6;
        unsigned z = n * 64u + zero_off + ((j & 63u) >> 2);
        float4 zv = make_float4(0.f, 0.f, 0.f, 0.f);
        out[z]     = zv;
        out[z + 1] = zv;
    }
}

// ---------------------------------------------------------------------------
// Kernel A: three block roles interleaved by a Bresenham split so memory-
// bound init blocks co-reside with ALU-bound edge/mask blocks:
//   mem  (NB_INIT): out slice0 = embeddings, slice1 = 0
//   alu  (NB_EDGE): edge dropout + compaction for all 3 hops
//   alu  (NB_MASK): message-dropout mask for hop 0
// ---------------------------------------------------------------------------
__global__ void k_A(const float4* __restrict__ ue, const float4* __restrict__ ie,
                    float4* __restrict__ out,
                    const float4* __restrict__ vals,
                    const int4*  __restrict__ rows,
                    const int4*  __restrict__ cols,
                    uint32_t ke00, uint32_t ke01,
                    uint32_t ke10, uint32_t ke11,
                    uint32_t ke20, uint32_t ke21,
                    uint32_t km00, uint32_t km01,
                    uint32_t one)
{
    unsigned bid = blockIdx.x;
    unsigned long long pp = (unsigned long long)bid * NB_INIT;
    unsigned before = (unsigned)(pp / NB_A);
    unsigned after  = (unsigned)((pp + NB_INIT) / NB_A);

    if (after > before) {
        // ---- mem role: init ----
        int i = (int)before * 256 + threadIdx.x;   // over ND/4, exact
        int node = i >> 4;
        int q    = i & 15;
        float4 v = (node < N_USERS) ? ue[node * 16 + q]
                                    : ie[(node - N_USERS) * 16 + q];
        unsigned o = (unsigned)node * 64u + (unsigned)q;
        out[o]      = v;
        out[o + 16] = make_float4(0.f, 0.f, 0.f, 0.f);
        return;
    }

    unsigned aid = bid - before;          // [0, NB_EDGE + NB_MASK)
    if (aid >= NB_EDGE) {
        // ---- alu role: mask for hop 0 ----
        int t = (int)(aid - NB_EDGE) * 256 + threadIdx.x;
        maskgen_body(t, g_mask[0], out, 0u, km00, km01, one);
        return;
    }

    // ---- alu role: edge dropout + compaction, 4 edges/thread, 3 hops ----
    int t    = (int)aid * 256 + threadIdx.x;
    int lane = threadIdx.x & 31;
    bool live = (t < NNZ / 4);

    float4 v  = make_float4(0.f, 0.f, 0.f, 0.f);
    int4   rr = make_int4(0, 0, 0, 0), cc = make_int4(0, 0, 0, 0);
    if (live) { v = vals[t]; rr = rows[t]; cc = cols[t]; }
    float vv[4] = {v.x, v.y, v.z, v.w};
    int   ra[4] = {rr.x, rr.y, rr.z, rr.w};
    int   ca[4] = {cc.x, cc.y, cc.z, cc.w};
    uint32_t j  = (uint32_t)t * 4u;

    uint32_t K0[3] = {ke00, ke10, ke20};
    uint32_t K1[3] = {ke01, ke11, ke21};

#pragma unroll
    for (int h = 0; h < N_HOPS; h++) {
        uint32_t ks2 = K0[h] ^ K1[h] ^ 0x1BD11BDAu;
        int4 e[4];
        int kept = 0;
        if (live) {
#pragma unroll
            for (int i = 0; i < 4; i++) {
                uint32_t b = tf_bits_i(K0[h], K1[h], ks2, j + (uint32_t)i, one);
                if ((int)b < 0) {                     // keep: u >= 0.5
                    e[kept] = make_int4(ra[i], ca[i],
                                        __float_as_int(vv[i] * 2.0f), 0);
                    kept++;
                }
            }
        }
        int off = kept;
#pragma unroll
        for (int d = 1; d < 32; d <<= 1) {
            int nn = __shfl_up_sync(0xFFFFFFFFu, off, d);
            if (lane >= d) off += nn;
        }
        int total = __shfl_sync(0xFFFFFFFFu, off, 31);
        int base  = 0;
        if (lane == 31 && total > 0) base = atomicAdd(&g_cnt[h], total);
        base = __shfl_sync(0xFFFFFFFFu, base, 31);

        int pos = base + off - kept;
#pragma unroll
        for (int i = 0; i < 4; i++)
            if (i < kept) g_edges[h][pos + i] = e[i];
    }
}

// ---------------------------------------------------------------------------
// Kernel B (per hop): spmm blocks (scatter with INLINE message-dropout mask)
// interleaved with maskgen blocks for the NEXT hop (and deferred zeroing of
// the next hop's destination slice).  nb_total == NB_SPMM -> spmm only.
// ---------------------------------------------------------------------------
__global__ void __launch_bounds__(256, 5)
k_B(float4* __restrict__ out,
    const float4* __restrict__ ue, const float4* __restrict__ ie,
    int hop, unsigned src_off, unsigned dst_off,
    unsigned nb_total, unsigned zero_off,
    uint32_t mk0, uint32_t mk1, uint32_t one)
{
    unsigned bid = blockIdx.x;
    unsigned long long pp = (unsigned long long)bid * NB_SPMM;
    unsigned before = (unsigned)(pp / nb_total);
    unsigned after  = (unsigned)((pp + NB_SPMM) / nb_total);

    if (after == before) {
        // ---- maskgen role for hop+1 (+ zero slice hop+2) ----
        int t = (int)(bid - before) * 256 + threadIdx.x;
        maskgen_body(t, g_mask[hop + 1], out, zero_off, mk0, mk1, one);
        return;
    }

    // ---- spmm role ----
    unsigned g  = before * 256u + threadIdx.x;
    int      eg = (int)(g >> 4);
    unsigned t  = g & 15u;
    int count = g_cnt[hop];
    int base  = eg * EPG;
    if (base >= count) return;
    int n = count - base; if (n > EPG) n = EPG;

    const int4* E = g_edges[hop];
    const uint8_t* M = g_mask[hop];
    int4 m[EPG];
#pragma unroll
    for (int i = 0; i < EPG; i++)
        if (i < n) m[i] = E[base + i];

    float4 a[EPG];
    uint32_t w[EPG];
#pragma unroll
    for (int i = 0; i < EPG; i++) {
        if (i < n) {
            unsigned c = (unsigned)m[i].y;
            const float4* p;
            if (hop == 0)
                p = (c < N_USERS) ? (ue + c * 16u)
                                  : (ie + (c - N_USERS) * 16u);
            else
                p = out + (c * 64u + src_off);
            a[i] = p[t];
            w[i] = *(const uint32_t*)(M + (unsigned)m[i].x * 64u + t * 4u);
        }
    }

    const float s = 1.0f / 0.9f;
#pragma unroll
    for (int i = 0; i < EPG; i++) {
        if (i < n) {
            float vs = __int_as_float(m[i].z) * s;
            float f0 = (w[i] & 0x000000FFu) ? vs : 0.0f;
            float f1 = (w[i] & 0x0000FF00u) ? vs : 0.0f;
            float f2 = (w[i] & 0x00FF0000u) ? vs : 0.0f;
            float f3 = (w[i] & 0xFF000000u) ? vs : 0.0f;
            float4* d = out + ((unsigned)m[i].x * 64u + dst_off + t);
            asm volatile("red.global.add.v4.f32 [%0], {%1, %2, %3, %4};"
                         :: "l"(d), "f"(a[i].x * f0), "f"(a[i].y * f1),
                            "f"(a[i].z * f2), "f"(a[i].w * f3)
                         : "memory");
        }
    }
}

// Tail: clear counters for the next graph replay (cannot be done inside k_B
// for hop 2 -- racy against its own g_cnt reads).
__global__ void k_tail()
{
    if (threadIdx.x < 4) g_cnt[threadIdx.x] = 0;
}

// ---------------------------------------------------------------------------
// Launch
// ---------------------------------------------------------------------------
extern "C" void kernel_launch(void* const* d_in, const int* in_sizes, int n_in,
                              void* d_out, int out_size)
{
    const float4* ue   = (const float4*)d_in[0];
    const float4* ie   = (const float4*)d_in[1];
    const int4*   rows = (const int4*)d_in[2];
    const int4*   cols = (const int4*)d_in[3];
    const float4* vals = (const float4*)d_in[4];
    float4*       out  = (float4*)d_out;

    // Partitionable ("fold-like") split: split(key,3)[i] = threefry(key, (0,i))
    uint32_t key0 = 0u, key1 = 42u;   // jax.random.key(42)
    uint32_t ke[N_HOPS][2], km[N_HOPS][2];
    for (int h = 0; h < N_HOPS; h++) {
        uint32_t n0, n1;
        threefry2x32_host(key0, key1, 0u, 0u, n0, n1);
        threefry2x32_host(key0, key1, 0u, 1u, ke[h][0], ke[h][1]);
        threefry2x32_host(key0, key1, 0u, 2u, km[h][0], km[h][1]);
        key0 = n0; key1 = n1;
    }

    const int B = 256;
    const uint32_t one = 1u;   // runtime-opaque multiplier for IMAD adds

    k_A<<<NB_A, B>>>(ue, ie, out, vals, rows, cols,
                     ke[0][0], ke[0][1], ke[1][0], ke[1][1], ke[2][0], ke[2][1],
                     km[0][0], km[0][1], one);

    // B0: spmm hop0 + maskgen hop1 + zero slice2
    k_B<<<NB_B, B>>>(out, ue, ie, 0, 0u, 16u, NB_B, 32u,
                     km[1][0], km[1][1], one);
    // B1: spmm hop1 + maskgen hop2 + zero slice3
    k_B<<<NB_B, B>>>(out, ue, ie, 1, 16u, 32u, NB_B, 48u,
                     km[2][0], km[2][1], one);
    // B2: spmm hop2 only
    k_B<<<NB_SPMM, B>>>(out, ue, ie, 2, 32u, 48u, NB_SPMM, 0u,
                        0u, 0u, one);

    k_tail<<<1, 32>>>();
}